// round 9
// baseline (speedup 1.0000x reference)
#include <cuda_runtime.h>
#include <cuda_bf16.h>

// Problem constants
#define TT   8192
#define LL   16
#define EWD  256
#define ECD  64
#define HH   512
#define HH2  128
#define NTAG 64
#define RCTA 32            // recurrence CTAs

// Scratch (allocation-free rule: __device__ globals)
__device__ float g_char_h[TT * HH2];          // 4 MB  final char-LSTM hidden per word
__device__ float g_xf[TT * 4 * HH];           // 64 MB precomputed Wih_f part of word gates
__device__ float g_hseq[TT * HH];             // 16 MB word-LSTM hidden per step
__device__ unsigned long long g_hpack[2][HH]; // {h (hi32), tag (lo32)} parity-buffered

__device__ __forceinline__ float sigf(float x) {
    return __fdividef(1.f, 1.f + __expf(-x));
}
__device__ __forceinline__ float tanh_f(float x) {
    return __fdividef(2.f, 1.f + __expf(-2.f * x)) - 1.f;
}

// ---------------------------------------------------------------------------
// Fused char LSTM: one CTA owns 32 words, loops all 16 char steps locally.
// ---------------------------------------------------------------------------
__global__ __launch_bounds__(512, 2) void char_fused_kernel(
    const int* __restrict__ seq_chars, const float* __restrict__ emb_char,
    const float* __restrict__ Wih_c, const float* __restrict__ Whh_c,
    const float* __restrict__ b_c)
{
    __shared__ float hs[32][128];    // 16 KB  h state
    __shared__ float Ae[32][64];     // 8 KB   char embeddings for current step
    __shared__ float Bs[8][512];     // 16 KB  weight chunk
    __shared__ int   chs[32][16];    // 2 KB

    const int tid = threadIdx.x;
    const int tx = tid & 31, ty = tid >> 5;   // ty 0..15
    const int r0 = blockIdx.x * 32;

    {   // char ids: 512 ints, 1/thread, coalesced
        int r = tid >> 4, ss = tid & 15;
        chs[r][ss] = seq_chars[(r0 + r) * LL + ss];
    }
    float creg[2][4];
#pragma unroll
    for (int rr = 0; rr < 2; rr++)
#pragma unroll
        for (int j = 0; j < 4; j++) creg[rr][j] = 0.f;

    for (int s = 0; s < LL; s++) {
        __syncthreads();   // orders prev-step hs writes / chs before reads below
#pragma unroll
        for (int i = 0; i < 4; i++) {
            int e = tid + i * 512;
            int r = e >> 6, k = e & 63;
            Ae[r][k] = emb_char[chs[r][s] * ECD + k];
        }
        float acc[2][16];
#pragma unroll
        for (int j = 0; j < 16; j++) {
            float bj = __ldg(&b_c[tx + 32 * j]);
            acc[0][j] = bj; acc[1][j] = bj;
        }
        // ---- emb chunks (K 0..63) ----
        for (int kc = 0; kc < 8; kc++) {
            const int k0 = kc * 8;
            {
                int n = tid;
                const float* src = Wih_c + n * ECD + k0;
#pragma unroll
                for (int q = 0; q < 2; q++) {
                    float4 v = *reinterpret_cast<const float4*>(src + q * 4);
                    Bs[q * 4 + 0][n] = v.x; Bs[q * 4 + 1][n] = v.y;
                    Bs[q * 4 + 2][n] = v.z; Bs[q * 4 + 3][n] = v.w;
                }
            }
            __syncthreads();
#pragma unroll
            for (int kk = 0; kk < 8; kk++) {
                float a0 = Ae[ty * 2 + 0][k0 + kk];
                float a1 = Ae[ty * 2 + 1][k0 + kk];
#pragma unroll
                for (int j = 0; j < 16; j++) {
                    float bv = Bs[kk][tx + 32 * j];
                    acc[0][j] += a0 * bv; acc[1][j] += a1 * bv;
                }
            }
            __syncthreads();
        }
        // ---- h chunks (K 0..127 of Whh) ----
        if (s > 0) {
            for (int kc = 0; kc < 16; kc++) {
                const int k0 = kc * 8;
                {
                    int n = tid;
                    const float* src = Whh_c + n * HH2 + k0;
#pragma unroll
                    for (int q = 0; q < 2; q++) {
                        float4 v = *reinterpret_cast<const float4*>(src + q * 4);
                        Bs[q * 4 + 0][n] = v.x; Bs[q * 4 + 1][n] = v.y;
                        Bs[q * 4 + 2][n] = v.z; Bs[q * 4 + 3][n] = v.w;
                    }
                }
                __syncthreads();
#pragma unroll
                for (int kk = 0; kk < 8; kk++) {
                    float a0 = hs[ty * 2 + 0][k0 + kk];
                    float a1 = hs[ty * 2 + 1][k0 + kk];
#pragma unroll
                    for (int j = 0; j < 16; j++) {
                        float bv = Bs[kk][tx + 32 * j];
                        acc[0][j] += a0 * bv; acc[1][j] += a1 * bv;
                    }
                }
                __syncthreads();
            }
        }
        // ---- pointwise LSTM update
#pragma unroll
        for (int rr = 0; rr < 2; rr++) {
#pragma unroll
            for (int j0 = 0; j0 < 4; j0++) {
                int mm = tx + 32 * j0;
                float gi = acc[rr][j0];
                float gf = acc[rr][j0 + 4];
                float gg = acc[rr][j0 + 8];
                float go = acc[rr][j0 + 12];
                float cnew = sigf(gf) * creg[rr][j0] + sigf(gi) * tanh_f(gg);
                float hnew = sigf(go) * tanh_f(cnew);
                creg[rr][j0] = cnew;
                hs[ty * 2 + rr][mm] = hnew;
            }
        }
    }
    __syncthreads();
#pragma unroll
    for (int i = 0; i < 8; i++) {
        int e = tid + i * 512;
        int r = e >> 7, k = e & 127;
        g_char_h[(r0 + r) * HH2 + k] = hs[r][k];
    }
}

// ---------------------------------------------------------------------------
// Word LSTM input GEMM: g_xf[t,n] = [ew[t], h_char[t]] · Wih_f[n,:] + b_f[n]
// ---------------------------------------------------------------------------
__global__ __launch_bounds__(256) void word_xgemm_kernel(
    const int* __restrict__ sentence, const float* __restrict__ emb_word,
    const float* __restrict__ Wih_f, const float* __restrict__ b_f)
{
    __shared__ float At[64][16];
    __shared__ float Bs[16][128];
    __shared__ int   wids[64];

    const int tid = threadIdx.x;
    const int tx = tid & 31, ty = tid >> 5;
    const int r0 = blockIdx.x * 64;
    const int c0 = blockIdx.y * 128;

    if (tid < 64) wids[tid] = sentence[r0 + tid];

    float acc[8][4];
#pragma unroll
    for (int r = 0; r < 8; r++)
#pragma unroll
        for (int j = 0; j < 4; j++) acc[r][j] = 0.f;
    __syncthreads();

    for (int kc = 0; kc < 24; kc++) {
        const int k0 = kc * 16;
#pragma unroll
        for (int i = 0; i < 4; i++) {          // A: 1024 elems, gathered
            int e = tid + i * 256;
            int r = e >> 4, kk = e & 15;
            int k = k0 + kk;
            float v;
            if (k < EWD) v = emb_word[wids[r] * EWD + k];
            else         v = g_char_h[(r0 + r) * HH2 + (k - EWD)];
            At[r][kk] = v;
        }
        {                                       // B: 2048 elems
            int n = tid & 127, kh = tid >> 7;
            const float* src = Wih_f + (c0 + n) * 384 + k0 + kh * 8;
#pragma unroll
            for (int q = 0; q < 2; q++) {
                float4 v = *reinterpret_cast<const float4*>(src + q * 4);
                int kk = kh * 8 + q * 4;
                Bs[kk + 0][n] = v.x; Bs[kk + 1][n] = v.y;
                Bs[kk + 2][n] = v.z; Bs[kk + 3][n] = v.w;
            }
        }
        __syncthreads();
#pragma unroll
        for (int kk = 0; kk < 16; kk++) {
            float av[8];
#pragma unroll
            for (int r = 0; r < 8; r++) av[r] = At[ty * 8 + r][kk];
#pragma unroll
            for (int j = 0; j < 4; j++) {
                float bv = Bs[kk][tx + 32 * j];
#pragma unroll
                for (int r = 0; r < 8; r++) acc[r][j] += av[r] * bv;
            }
        }
        __syncthreads();
    }
#pragma unroll
    for (int j = 0; j < 4; j++) {
        int n = c0 + tx + 32 * j;
        float bj = __ldg(&b_f[n]);
#pragma unroll
        for (int r = 0; r < 8; r++)
            g_xf[(r0 + ty * 8 + r) * 2048 + n] = acc[r][j] + bj;
    }
}

// ---------------------------------------------------------------------------
// Word LSTM recurrence v4: tagged-value handshake, one __syncthreads per step.
// 32 CTAs x 512 threads = 512 warps; warp owns h-element m.
// Producer (lane0): st.release.gpu.u64 {h, tag=t+1} into g_hpack[t&1][m].
// Consumer (every thread): spins ld.acquire.gpu.u64 on its OWN slot
// g_hpack[(t-1)&1][tid] until tag==t — the h value arrives with the tag
// (no separate flag, no separate h-load round). Then STS into the
// parity-matching hsm buffer, one bar, LDS-fed FMAs, shfl reduce, gates.
// Safety: 1-based exact-match tags (zero-init / stale replay tags never
// match); 2-deep parity ring cannot clobber an unobserved tag (producer's
// bar(t+2) transitively requires every CTA's bar(t+1), which required
// observing tag t+1). Graph replays need no reset kernel.
// ---------------------------------------------------------------------------
__global__ __launch_bounds__(512) void word_recur_kernel(const float* __restrict__ Whh_f)
{
    __shared__ float hsm[2][HH];

    const int tid = threadIdx.x;
    const int l = tid & 31;
    const int w = tid >> 5;                 // 0..15
    const int m = blockIdx.x * 16 + w;
    const unsigned FULL = 0xffffffffu;

    float wt[4][16];
#pragma unroll
    for (int g = 0; g < 4; g++)
#pragma unroll
        for (int j = 0; j < 16; j++)
            wt[g][j] = __ldg(&Whh_f[(g * HH + m) * HH + j * 32 + l]);

    float c = 0.f;
    float x0 = 0.f, x1 = 0.f, x2 = 0.f, x3 = 0.f;
    if (l == 0) {
        const float* xp = g_xf + m;
        x0 = __ldg(xp); x1 = __ldg(xp + HH);
        x2 = __ldg(xp + 2 * HH); x3 = __ldg(xp + 3 * HH);
    }

    for (int t = 0; t < TT; t++) {
        const int pb = t & 1;               // parity buffer receiving h(t)
        if (t > 0) {
            // spin on own slot: h(t-1) tagged t, parity pb^1
            unsigned long long* sp = &g_hpack[pb ^ 1][tid];
            const unsigned tgt = (unsigned)t;
            unsigned long long v;
            do {
                asm volatile("ld.acquire.gpu.global.u64 %0, [%1];"
                             : "=l"(v) : "l"(sp) : "memory");
            } while ((unsigned)v != tgt);
            hsm[pb ^ 1][tid] = __uint_as_float((unsigned)(v >> 32));
        }
        __syncthreads();                    // the ONLY barrier per step

        float a0 = 0.f, a1 = 0.f, a2 = 0.f, a3 = 0.f;
        if (t > 0) {
            const float* hrow = hsm[pb ^ 1];
#pragma unroll
            for (int j = 0; j < 16; j++) {
                float hv = hrow[j * 32 + l];
                a0 += wt[0][j] * hv; a1 += wt[1][j] * hv;
                a2 += wt[2][j] * hv; a3 += wt[3][j] * hv;
            }
        }
#pragma unroll
        for (int off = 16; off > 0; off >>= 1) {
            a0 += __shfl_xor_sync(FULL, a0, off);
            a1 += __shfl_xor_sync(FULL, a1, off);
            a2 += __shfl_xor_sync(FULL, a2, off);
            a3 += __shfl_xor_sync(FULL, a3, off);
        }
        if (l == 0) {
            float ig = sigf(a0 + x0);
            float fg = sigf(a1 + x1);
            float gg = tanh_f(a2 + x2);
            float og = sigf(a3 + x3);
            c = fg * c + ig * gg;
            float h = og * tanh_f(c);
            __stcg(&g_hseq[t * HH + m], h);           // for the tagger
            if (t < TT - 1) {
                unsigned long long pv =
                    ((unsigned long long)__float_as_uint(h) << 32) |
                    (unsigned long long)(unsigned)(t + 1);
                asm volatile("st.release.gpu.global.u64 [%0], %1;"
                             :: "l"(&g_hpack[pb][m]), "l"(pv) : "memory");
                const float* xp = g_xf + (t + 1) * 2048 + m;   // prefetch x(t+1)
                x0 = __ldg(xp); x1 = __ldg(xp + HH);
                x2 = __ldg(xp + 2 * HH); x3 = __ldg(xp + 3 * HH);
            }
        }
    }
}

// ---------------------------------------------------------------------------
// Tagger: out[t,k] = log_softmax(h_seq[t]·W_tag[k,:] + b_tag[k]) over 64 tags
// ---------------------------------------------------------------------------
__global__ __launch_bounds__(256) void tagger_kernel(
    const float* __restrict__ W_tag, const float* __restrict__ b_tag,
    float* __restrict__ out)
{
    __shared__ float Wt[128][65];
    __shared__ float hs[16][128];
    __shared__ float red[8];

    const int tid = threadIdx.x;
    const int k = tid & 63, rg = tid >> 6;  // rg 0..3
    const int r0 = blockIdx.x * 16;
    const int wid = tid >> 5, lane = tid & 31;

    float acc[4] = {0.f, 0.f, 0.f, 0.f};
    for (int kc = 0; kc < 4; kc++) {
        const int k0 = kc * 128;
#pragma unroll 8
        for (int i = 0; i < 32; i++) {
            int e = tid + 256 * i;
            int kt = e >> 7, j = e & 127;
            Wt[j][kt] = W_tag[kt * HH + k0 + j];
        }
#pragma unroll
        for (int i = 0; i < 8; i++) {
            int e = tid + 256 * i;
            int r = e >> 7, j = e & 127;
            hs[r][j] = g_hseq[(r0 + r) * HH + k0 + j];
        }
        __syncthreads();
#pragma unroll
        for (int i = 0; i < 4; i++) {
            int r = rg + 4 * i;
            float a = 0.f;
#pragma unroll 8
            for (int j = 0; j < 128; j++) a += hs[r][j] * Wt[j][k];
            acc[i] += a;
        }
        __syncthreads();
    }

    const float bt = __ldg(&b_tag[k]);
    for (int i = 0; i < 4; i++) {
        const int r = r0 + rg + 4 * i;
        float logit = acc[i] + bt;
        float mx = logit;
#pragma unroll
        for (int off = 16; off; off >>= 1)
            mx = fmaxf(mx, __shfl_xor_sync(0xffffffffu, mx, off));
        if (lane == 0) red[wid] = mx;
        __syncthreads();
        mx = fmaxf(red[rg * 2], red[rg * 2 + 1]);
        __syncthreads();
        float e = __expf(logit - mx);
        float sm = e;
#pragma unroll
        for (int off = 16; off; off >>= 1)
            sm += __shfl_xor_sync(0xffffffffu, sm, off);
        if (lane == 0) red[wid] = sm;
        __syncthreads();
        sm = red[rg * 2] + red[rg * 2 + 1];
        __syncthreads();
        out[r * NTAG + k] = logit - mx - logf(sm);
    }
}

// ---------------------------------------------------------------------------
extern "C" void kernel_launch(void* const* d_in, const int* in_sizes, int n_in,
                              void* d_out, int out_size)
{
    const int*   sentence  = (const int*)  d_in[0];
    const int*   seq_chars = (const int*)  d_in[1];
    const float* emb_word  = (const float*)d_in[2];
    const float* emb_char  = (const float*)d_in[3];
    const float* Wih_c     = (const float*)d_in[4];
    const float* Whh_c     = (const float*)d_in[5];
    const float* b_c       = (const float*)d_in[6];
    const float* Wih_f     = (const float*)d_in[7];
    const float* Whh_f     = (const float*)d_in[8];
    const float* b_f       = (const float*)d_in[9];
    const float* W_tag     = (const float*)d_in[10];
    const float* b_tag     = (const float*)d_in[11];
    float* out = (float*)d_out;

    char_fused_kernel<<<TT / 32, 512>>>(seq_chars, emb_char, Wih_c, Whh_c, b_c);

    word_xgemm_kernel<<<dim3(TT / 64, 2048 / 128), 256>>>(sentence, emb_word, Wih_f, b_f);

    word_recur_kernel<<<RCTA, 512>>>(Whh_f);

    tagger_kernel<<<TT / 16, 256>>>(W_tag, b_tag, out);
}

// round 14
// speedup vs baseline: 1.1849x; 1.1849x over previous
#include <cuda_runtime.h>
#include <cuda_bf16.h>

// Problem constants
#define TT   8192
#define LL   16
#define EWD  256
#define ECD  64
#define HH   512
#define HH2  128
#define NTAG 64
#define RCTA 32            // recurrence CTAs (R6-proven shape)

// Scratch (allocation-free rule: __device__ globals)
__device__ float g_char_h[TT * HH2];        // 4 MB  final char-LSTM hidden per word
__device__ float g_xf[TT * 4 * HH];         // 64 MB precomputed Wih_f part of word gates
__device__ float g_hseq[TT * HH];           // 16 MB word-LSTM hidden per step
__device__ unsigned g_flags[RCTA];          // per-CTA progress flags

__device__ __forceinline__ float sigf(float x) {
    return __fdividef(1.f, 1.f + __expf(-x));
}
__device__ __forceinline__ float tanh_f(float x) {
    return __fdividef(2.f, 1.f + __expf(-2.f * x)) - 1.f;
}

// packed f32x2 fma: d = a*b + d   (Blackwell FFMA2, PTX-only)
__device__ __forceinline__ void fma2(unsigned long long& d,
                                     unsigned long long a, unsigned long long b) {
    asm("fma.rn.f32x2 %0, %1, %2, %3;" : "=l"(d) : "l"(a), "l"(b), "l"(d));
}
__device__ __forceinline__ float hsum2(unsigned long long v) {
    float lo, hi;
    asm("mov.b64 {%0,%1}, %2;" : "=f"(lo), "=f"(hi) : "l"(v));
    return lo + hi;
}

// ---------------------------------------------------------------------------
// Fused char LSTM: one CTA owns 32 words, loops all 16 char steps locally.
// ---------------------------------------------------------------------------
__global__ __launch_bounds__(512, 2) void char_fused_kernel(
    const int* __restrict__ seq_chars, const float* __restrict__ emb_char,
    const float* __restrict__ Wih_c, const float* __restrict__ Whh_c,
    const float* __restrict__ b_c)
{
    __shared__ float hs[32][128];    // 16 KB  h state
    __shared__ float Ae[32][64];     // 8 KB   char embeddings for current step
    __shared__ float Bs[8][512];     // 16 KB  weight chunk
    __shared__ int   chs[32][16];    // 2 KB

    const int tid = threadIdx.x;
    const int tx = tid & 31, ty = tid >> 5;   // ty 0..15
    const int r0 = blockIdx.x * 32;

    {   // char ids: 512 ints, 1/thread, coalesced
        int r = tid >> 4, ss = tid & 15;
        chs[r][ss] = seq_chars[(r0 + r) * LL + ss];
    }
    float creg[2][4];
#pragma unroll
    for (int rr = 0; rr < 2; rr++)
#pragma unroll
        for (int j = 0; j < 4; j++) creg[rr][j] = 0.f;

    for (int s = 0; s < LL; s++) {
        __syncthreads();   // orders prev-step hs writes / chs before reads below
#pragma unroll
        for (int i = 0; i < 4; i++) {
            int e = tid + i * 512;
            int r = e >> 6, k = e & 63;
            Ae[r][k] = emb_char[chs[r][s] * ECD + k];
        }
        float acc[2][16];
#pragma unroll
        for (int j = 0; j < 16; j++) {
            float bj = __ldg(&b_c[tx + 32 * j]);
            acc[0][j] = bj; acc[1][j] = bj;
        }
        // ---- emb chunks (K 0..63) ----
        for (int kc = 0; kc < 8; kc++) {
            const int k0 = kc * 8;
            {
                int n = tid;
                const float* src = Wih_c + n * ECD + k0;
#pragma unroll
                for (int q = 0; q < 2; q++) {
                    float4 v = *reinterpret_cast<const float4*>(src + q * 4);
                    Bs[q * 4 + 0][n] = v.x; Bs[q * 4 + 1][n] = v.y;
                    Bs[q * 4 + 2][n] = v.z; Bs[q * 4 + 3][n] = v.w;
                }
            }
            __syncthreads();
#pragma unroll
            for (int kk = 0; kk < 8; kk++) {
                float a0 = Ae[ty * 2 + 0][k0 + kk];
                float a1 = Ae[ty * 2 + 1][k0 + kk];
#pragma unroll
                for (int j = 0; j < 16; j++) {
                    float bv = Bs[kk][tx + 32 * j];
                    acc[0][j] += a0 * bv; acc[1][j] += a1 * bv;
                }
            }
            __syncthreads();
        }
        // ---- h chunks (K 0..127 of Whh) ----
        if (s > 0) {
            for (int kc = 0; kc < 16; kc++) {
                const int k0 = kc * 8;
                {
                    int n = tid;
                    const float* src = Whh_c + n * HH2 + k0;
#pragma unroll
                    for (int q = 0; q < 2; q++) {
                        float4 v = *reinterpret_cast<const float4*>(src + q * 4);
                        Bs[q * 4 + 0][n] = v.x; Bs[q * 4 + 1][n] = v.y;
                        Bs[q * 4 + 2][n] = v.z; Bs[q * 4 + 3][n] = v.w;
                    }
                }
                __syncthreads();
#pragma unroll
                for (int kk = 0; kk < 8; kk++) {
                    float a0 = hs[ty * 2 + 0][k0 + kk];
                    float a1 = hs[ty * 2 + 1][k0 + kk];
#pragma unroll
                    for (int j = 0; j < 16; j++) {
                        float bv = Bs[kk][tx + 32 * j];
                        acc[0][j] += a0 * bv; acc[1][j] += a1 * bv;
                    }
                }
                __syncthreads();
            }
        }
        // ---- pointwise LSTM update
#pragma unroll
        for (int rr = 0; rr < 2; rr++) {
#pragma unroll
            for (int j0 = 0; j0 < 4; j0++) {
                int mm = tx + 32 * j0;
                float gi = acc[rr][j0];
                float gf = acc[rr][j0 + 4];
                float gg = acc[rr][j0 + 8];
                float go = acc[rr][j0 + 12];
                float cnew = sigf(gf) * creg[rr][j0] + sigf(gi) * tanh_f(gg);
                float hnew = sigf(go) * tanh_f(cnew);
                creg[rr][j0] = cnew;
                hs[ty * 2 + rr][mm] = hnew;
            }
        }
    }
    __syncthreads();
#pragma unroll
    for (int i = 0; i < 8; i++) {
        int e = tid + i * 512;
        int r = e >> 7, k = e & 127;
        g_char_h[(r0 + r) * HH2 + k] = hs[r][k];
    }
}

// ---------------------------------------------------------------------------
// Word LSTM input GEMM: g_xf[t,n] = [ew[t], h_char[t]] · Wih_f[n,:] + b_f[n]
// ---------------------------------------------------------------------------
__global__ __launch_bounds__(256) void word_xgemm_kernel(
    const int* __restrict__ sentence, const float* __restrict__ emb_word,
    const float* __restrict__ Wih_f, const float* __restrict__ b_f)
{
    __shared__ float At[64][16];
    __shared__ float Bs[16][128];
    __shared__ int   wids[64];

    const int tid = threadIdx.x;
    const int tx = tid & 31, ty = tid >> 5;
    const int r0 = blockIdx.x * 64;
    const int c0 = blockIdx.y * 128;

    if (tid < 64) wids[tid] = sentence[r0 + tid];

    float acc[8][4];
#pragma unroll
    for (int r = 0; r < 8; r++)
#pragma unroll
        for (int j = 0; j < 4; j++) acc[r][j] = 0.f;
    __syncthreads();

    for (int kc = 0; kc < 24; kc++) {
        const int k0 = kc * 16;
#pragma unroll
        for (int i = 0; i < 4; i++) {          // A: 1024 elems, gathered
            int e = tid + i * 256;
            int r = e >> 4, kk = e & 15;
            int k = k0 + kk;
            float v;
            if (k < EWD) v = emb_word[wids[r] * EWD + k];
            else         v = g_char_h[(r0 + r) * HH2 + (k - EWD)];
            At[r][kk] = v;
        }
        {                                       // B: 2048 elems
            int n = tid & 127, kh = tid >> 7;
            const float* src = Wih_f + (c0 + n) * 384 + k0 + kh * 8;
#pragma unroll
            for (int q = 0; q < 2; q++) {
                float4 v = *reinterpret_cast<const float4*>(src + q * 4);
                int kk = kh * 8 + q * 4;
                Bs[kk + 0][n] = v.x; Bs[kk + 1][n] = v.y;
                Bs[kk + 2][n] = v.z; Bs[kk + 3][n] = v.w;
            }
        }
        __syncthreads();
#pragma unroll
        for (int kk = 0; kk < 16; kk++) {
            float av[8];
#pragma unroll
            for (int r = 0; r < 8; r++) av[r] = At[ty * 8 + r][kk];
#pragma unroll
            for (int j = 0; j < 4; j++) {
                float bv = Bs[kk][tx + 32 * j];
#pragma unroll
                for (int r = 0; r < 8; r++) acc[r][j] += av[r] * bv;
            }
        }
        __syncthreads();
    }
#pragma unroll
    for (int j = 0; j < 4; j++) {
        int n = c0 + tx + 32 * j;
        float bj = __ldg(&b_f[n]);
#pragma unroll
        for (int r = 0; r < 8; r++)
            g_xf[(r0 + ty * 8 + r) * 2048 + n] = acc[r][j] + bj;
    }
}

// ---------------------------------------------------------------------------
__global__ void reset_bar_kernel() {
    if (threadIdx.x < RCTA) g_flags[threadIdx.x] = 0u;
}

// ---------------------------------------------------------------------------
// Word LSTM recurrence v6: EXACT R6 shape + protocol (32 CTAs x 512 threads,
// warp owns h-element m; warp0 polls the 32 per-CTA flags on ONE line; CTA
// coop-stages h; release-store flag after CTA bar). Single change vs R6:
// packed fma.rn.f32x2 (FFMA2) + LDS.64 h-pairs + LDG.64 weight pairs —
// halves the compute-burst issue slots (128 -> 64 per warp per step).
// ---------------------------------------------------------------------------
__global__ __launch_bounds__(512) void word_recur_kernel(const float* __restrict__ Whh_f)
{
    __shared__ float2 hsm[HH / 2];          // h as 256 pairs

    const int tid = threadIdx.x;
    const int l = tid & 31;
    const int w = tid >> 5;                 // 0..15
    const int m = blockIdx.x * 16 + w;
    const unsigned FULL = 0xffffffffu;

    // packed weights: wt2[g][k] covers h positions {2*(32k+l), 2*(32k+l)+1}
    unsigned long long wt2[4][8];
#pragma unroll
    for (int g = 0; g < 4; g++) {
        const float2* wp = reinterpret_cast<const float2*>(Whh_f + (g * HH + m) * HH);
#pragma unroll
        for (int k = 0; k < 8; k++) {
            float2 v = __ldg(&wp[32 * k + l]);
            unsigned long long pv;
            asm("mov.b64 %0, {%1,%2};" : "=l"(pv) : "f"(v.x), "f"(v.y));
            wt2[g][k] = pv;
        }
    }

    float c = 0.f;
    float x0 = 0.f, x1 = 0.f, x2 = 0.f, x3 = 0.f;
    if (l == 0) {
        const float* xp = g_xf + m;
        x0 = __ldg(xp); x1 = __ldg(xp + HH);
        x2 = __ldg(xp + 2 * HH); x3 = __ldg(xp + 3 * HH);
    }

    for (int t = 0; t < TT; t++) {
        if (t > 0) {
            if (w == 0) {                   // warp0: poll all 32 CTA flags (1 line)
                unsigned* fp = &g_flags[l];
                const unsigned tgt = (unsigned)t;
                bool done;
                do {
                    unsigned v;
                    asm volatile("ld.acquire.gpu.global.u32 %0, [%1];"
                                 : "=r"(v) : "l"(fp) : "memory");
                    done = __all_sync(FULL, v >= tgt);
                } while (!done);
            }
            __syncthreads();                // release CTA once flags observed
            if (tid < HH / 2)               // coop stage: 256 float2 loads
                hsm[tid] = __ldcg(reinterpret_cast<const float2*>(
                    g_hseq + (t - 1) * HH) + tid);
            __syncthreads();
        }

        unsigned long long acc2[4] = {0ull, 0ull, 0ull, 0ull};
        if (t > 0) {
#pragma unroll
            for (int k = 0; k < 8; k++) {
                unsigned long long hp =
                    *reinterpret_cast<unsigned long long*>(&hsm[32 * k + l]);
                fma2(acc2[0], wt2[0][k], hp);
                fma2(acc2[1], wt2[1][k], hp);
                fma2(acc2[2], wt2[2][k], hp);
                fma2(acc2[3], wt2[3][k], hp);
            }
        }
        float a0 = hsum2(acc2[0]);
        float a1 = hsum2(acc2[1]);
        float a2 = hsum2(acc2[2]);
        float a3 = hsum2(acc2[3]);
#pragma unroll
        for (int off = 16; off > 0; off >>= 1) {
            a0 += __shfl_xor_sync(FULL, a0, off);
            a1 += __shfl_xor_sync(FULL, a1, off);
            a2 += __shfl_xor_sync(FULL, a2, off);
            a3 += __shfl_xor_sync(FULL, a3, off);
        }
        if (l == 0) {
            float ig = sigf(a0 + x0);
            float fg = sigf(a1 + x1);
            float gg = tanh_f(a2 + x2);
            float og = sigf(a3 + x3);
            c = fg * c + ig * gg;
            float h = og * tanh_f(c);
            __stcg(&g_hseq[t * HH + m], h);
        }
        __syncthreads();                    // all warps' h stores ordered (hb)
        if (t < TT - 1) {
            if (tid == 0)
                asm volatile("st.release.gpu.global.u32 [%0], %1;"
                             :: "l"(&g_flags[blockIdx.x]), "r"((unsigned)(t + 1))
                             : "memory");
            if (l == 0) {                   // prefetch xg for t+1
                const float* xp = g_xf + (t + 1) * 2048 + m;
                x0 = __ldg(xp); x1 = __ldg(xp + HH);
                x2 = __ldg(xp + 2 * HH); x3 = __ldg(xp + 3 * HH);
            }
        }
    }
}

// ---------------------------------------------------------------------------
// Tagger: out[t,k] = log_softmax(h_seq[t]·W_tag[k,:] + b_tag[k]) over 64 tags
// ---------------------------------------------------------------------------
__global__ __launch_bounds__(256) void tagger_kernel(
    const float* __restrict__ W_tag, const float* __restrict__ b_tag,
    float* __restrict__ out)
{
    __shared__ float Wt[128][65];
    __shared__ float hs[16][128];
    __shared__ float red[8];

    const int tid = threadIdx.x;
    const int k = tid & 63, rg = tid >> 6;  // rg 0..3
    const int r0 = blockIdx.x * 16;
    const int wid = tid >> 5, lane = tid & 31;

    float acc[4] = {0.f, 0.f, 0.f, 0.f};
    for (int kc = 0; kc < 4; kc++) {
        const int k0 = kc * 128;
#pragma unroll 8
        for (int i = 0; i < 32; i++) {
            int e = tid + 256 * i;
            int kt = e >> 7, j = e & 127;
            Wt[j][kt] = W_tag[kt * HH + k0 + j];
        }
#pragma unroll
        for (int i = 0; i < 8; i++) {
            int e = tid + 256 * i;
            int r = e >> 7, j = e & 127;
            hs[r][j] = g_hseq[(r0 + r) * HH + k0 + j];
        }
        __syncthreads();
#pragma unroll
        for (int i = 0; i < 4; i++) {
            int r = rg + 4 * i;
            float a = 0.f;
#pragma unroll 8
            for (int j = 0; j < 128; j++) a += hs[r][j] * Wt[j][k];
            acc[i] += a;
        }
        __syncthreads();
    }

    const float bt = __ldg(&b_tag[k]);
    for (int i = 0; i < 4; i++) {
        const int r = r0 + rg + 4 * i;
        float logit = acc[i] + bt;
        float mx = logit;
#pragma unroll
        for (int off = 16; off; off >>= 1)
            mx = fmaxf(mx, __shfl_xor_sync(0xffffffffu, mx, off));
        if (lane == 0) red[wid] = mx;
        __syncthreads();
        mx = fmaxf(red[rg * 2], red[rg * 2 + 1]);
        __syncthreads();
        float e = __expf(logit - mx);
        float sm = e;
#pragma unroll
        for (int off = 16; off; off >>= 1)
            sm += __shfl_xor_sync(0xffffffffu, sm, off);
        if (lane == 0) red[wid] = sm;
        __syncthreads();
        sm = red[rg * 2] + red[rg * 2 + 1];
        __syncthreads();
        out[r * NTAG + k] = logit - mx - logf(sm);
    }
}

// ---------------------------------------------------------------------------
extern "C" void kernel_launch(void* const* d_in, const int* in_sizes, int n_in,
                              void* d_out, int out_size)
{
    const int*   sentence  = (const int*)  d_in[0];
    const int*   seq_chars = (const int*)  d_in[1];
    const float* emb_word  = (const float*)d_in[2];
    const float* emb_char  = (const float*)d_in[3];
    const float* Wih_c     = (const float*)d_in[4];
    const float* Whh_c     = (const float*)d_in[5];
    const float* b_c       = (const float*)d_in[6];
    const float* Wih_f     = (const float*)d_in[7];
    const float* Whh_f     = (const float*)d_in[8];
    const float* b_f       = (const float*)d_in[9];
    const float* W_tag     = (const float*)d_in[10];
    const float* b_tag     = (const float*)d_in[11];
    float* out = (float*)d_out;

    char_fused_kernel<<<TT / 32, 512>>>(seq_chars, emb_char, Wih_c, Whh_c, b_c);

    word_xgemm_kernel<<<dim3(TT / 64, 2048 / 128), 256>>>(sentence, emb_word, Wih_f, b_f);

    reset_bar_kernel<<<1, 32>>>();
    word_recur_kernel<<<RCTA, 512>>>(Whh_f);

    tagger_kernel<<<TT / 16, 256>>>(W_tag, b_tag, out);
}